// round 4
// baseline (speedup 1.0000x reference)
#include <cuda_runtime.h>
#include <cstdint>

#define BATCH 16
#define HW    262144
#define NPIX  4194304

// ---------------- scratch (device globals; no runtime allocation) ----------
__device__ float g_qhi[NPIX], g_qlo[NPIX], g_khi[NPIX], g_klo[NPIX];   // [B,H,W]
__device__ float g_vT[BATCH * 8 * HW];                                 // [B,C,W,H]
__device__ float g_attn[BATCH * HW];                                   // [B,H,H]

// ---------------- helpers ---------------------------------------------------
__device__ __forceinline__ float tf32r(float x) {
    uint32_t u; asm("cvt.rna.tf32.f32 %0, %1;" : "=r"(u) : "f"(x));
    return __uint_as_float(u);
}
#define CPA16(s, g)   asm volatile("cp.async.cg.shared.global [%0], [%1], 16;" :: "r"(s), "l"(g) : "memory")
#define CPA_COMMIT()  asm volatile("cp.async.commit_group;" ::: "memory")
#define CPA_WAIT(n)   asm volatile("cp.async.wait_group %0;" :: "n"(n) : "memory")

__device__ __forceinline__ uint32_t smem_u32(const void* p) {
    uint32_t a;
    asm("{ .reg .u64 t; cvta.to.shared.u64 t, %1; cvt.u32.u64 %0, t; }" : "=r"(a) : "l"(p));
    return a;
}
// byte offset of element (row, col-float) in a [rows][32]-float K-major tile,
// XOR-swizzled so mma fragment reads are bank-conflict-free.
__device__ __forceinline__ uint32_t swz(int r, int c) {
    uint32_t o = (uint32_t)(r * 128 + c * 4);
    return o ^ ((o >> 3) & 0x70);
}
__device__ __forceinline__ uint32_t lds32(uint32_t a) {
    uint32_t v; asm volatile("ld.shared.b32 %0, [%1];" : "=r"(v) : "r"(a));
    return v;
}
#define MMA_TF32(c, a, b0, b1) \
    asm volatile("mma.sync.aligned.m16n8k8.row.col.f32.tf32.tf32.f32 " \
                 "{%0,%1,%2,%3},{%4,%5,%6,%7},{%8,%9},{%0,%1,%2,%3};" \
                 : "+f"((c)[0]), "+f"((c)[1]), "+f"((c)[2]), "+f"((c)[3]) \
                 : "r"((a)[0]), "r"((a)[1]), "r"((a)[2]), "r"((a)[3]), "r"(b0), "r"(b1))

// ---------------------------------------------------------------------------
// Fused q/k/v 1x1 convs.  q,k written as tf32 hi/lo pairs (3xTF32 logits),
// v transposed to [B,C,W,H] (tf32-rounded) via SMEM tile transpose.
// ---------------------------------------------------------------------------
__global__ void __launch_bounds__(256)
qkv_kernel(const float* __restrict__ x,
           const float* __restrict__ Wq, const float* __restrict__ bq,
           const float* __restrict__ Wk, const float* __restrict__ bk,
           const float* __restrict__ Wv, const float* __restrict__ bv)
{
    __shared__ float sWq[8], sWk[8], sWv[64], sBv[8], sB2[2];
    __shared__ float sv[8][32][33];
    const int tid = threadIdx.x;
    if (tid < 8) { sWq[tid] = Wq[tid]; sWk[tid] = Wk[tid]; sBv[tid] = bv[tid]; }
    if (tid >= 8 && tid < 72) sWv[tid - 8] = Wv[tid - 8];
    if (tid == 72) sB2[0] = bq[0];
    if (tid == 73) sB2[1] = bk[0];
    __syncthreads();

    const int b = blockIdx.z, h0 = blockIdx.y * 32, w0 = blockIdx.x * 32;
    const int j = tid & 31, i0 = tid >> 5;

    for (int ii = 0; ii < 4; ii++) {
        const int i = i0 + ii * 8;
        const int h = h0 + i, w = w0 + j;
        const size_t pb = ((size_t)b * 8) * HW + (size_t)h * 512 + w;
        float xv[8];
#pragma unroll
        for (int c = 0; c < 8; c++) xv[c] = x[pb + (size_t)c * HW];

        float q = sB2[0], k = sB2[1];
#pragma unroll
        for (int c = 0; c < 8; c++) { q += xv[c] * sWq[c]; k += xv[c] * sWk[c]; }
        const size_t p = (size_t)b * HW + (size_t)h * 512 + w;
        const float qh = tf32r(q), kh = tf32r(k);
        g_qhi[p] = qh; g_qlo[p] = tf32r(q - qh);
        g_khi[p] = kh; g_klo[p] = tf32r(k - kh);

#pragma unroll
        for (int o = 0; o < 8; o++) {
            float v = sBv[o];
#pragma unroll
            for (int c = 0; c < 8; c++) v += xv[c] * sWv[o * 8 + c];
            sv[o][i][j] = tf32r(v);
        }
    }
    __syncthreads();

    for (int ii = 0; ii < 4; ii++) {
        const int wl = i0 + ii * 8;   // local w
        const int hl = j;             // local h
#pragma unroll
        for (int c = 0; c < 8; c++) {
            g_vT[(((size_t)b * 8 + c) * 512 + (w0 + wl)) * 512 + (h0 + hl)] = sv[c][hl][wl];
        }
    }
}

// ---------------------------------------------------------------------------
// mma.sync tf32 GEMM: C[m,n] = sum_k A[m,k]*B[n,k], per-z 512x512x512.
// 512 threads, 16 warps in 4x4 grid. CTA tile 128 x BN, warp tile 32 x BN/4.
// K-chunk 32, 3-stage cp.async pipeline, XOR-swizzled SMEM.
// SPLIT: 3xTF32 using (Ahi,Alo,Bhi,Blo).
// ---------------------------------------------------------------------------
template <int BN, bool SPLIT>
__global__ void __launch_bounds__(512)
gemm_mma(const float* __restrict__ Ahi, const float* __restrict__ Alo,
         const float* __restrict__ Bhi, const float* __restrict__ Blo,
         float* __restrict__ Cb, int aShift)
{
    constexpr int STAGES = 3;
    constexpr uint32_t TA = 128 * 32 * 4;                    // 16 KB
    constexpr uint32_t TB = (uint32_t)BN * 32 * 4;
    constexpr uint32_t SB = (SPLIT ? 2u : 1u) * (TA + TB);   // stage bytes
    constexpr int NT = BN / 32;                              // n-tiles (of 8) per warp

    extern __shared__ char smem[];
    const uint32_t s0 = smem_u32(smem);

    const int tid  = threadIdx.x;
    const int lane = tid & 31;
    const int wid  = tid >> 5;
    const int wm   = (wid & 3) * 32;          // warp m offset
    const int wn   = (wid >> 2) * (BN / 4);   // warp n offset
    const int gid  = lane >> 2;               // fragment group id (0..7)
    const int tig  = lane & 3;                // thread in group  (0..3)

    const int z = blockIdx.z;
    const size_t m0 = (size_t)blockIdx.y * 128;
    const size_t n0 = (size_t)blockIdx.x * BN;
    const float* Ah = Ahi + (size_t)(z >> aShift) * HW;
    const float* Al = Alo + (size_t)(z >> aShift) * HW;
    const float* Bh = Bhi + (size_t)z * HW;
    const float* Bl = Blo + (size_t)z * HW;
    float* C = Cb + (size_t)z * HW;

    // loader mapping: 512 threads -> (seg 0..7) x (row0 0..63)
    const int seg  = tid & 7;
    const int row0 = tid >> 3;

    auto load_chunk = [&](int c) {
        const uint32_t base = s0 + (uint32_t)(c % STAGES) * SB;
        const size_t go = (size_t)c * 32 + seg * 4;
#pragma unroll
        for (int i = 0; i < 2; i++) {
            const int r = row0 + i * 64;
            const uint32_t sw = swz(r, seg * 4);
            CPA16(base + sw, Ah + (m0 + r) * 512 + go);
            if (SPLIT) CPA16(base + TA + TB + sw, Al + (m0 + r) * 512 + go);
        }
#pragma unroll
        for (int i = 0; i < BN / 64; i++) {
            const int r = row0 + i * 64;
            const uint32_t sw = swz(r, seg * 4);
            CPA16(base + TA + sw, Bh + (n0 + r) * 512 + go);
            if (SPLIT) CPA16(base + 2 * TA + TB + sw, Bl + (n0 + r) * 512 + go);
        }
    };

    float acc[2][NT][4] = {};

    // prologue
#pragma unroll
    for (int c = 0; c < STAGES - 1; c++) { load_chunk(c); CPA_COMMIT(); }

    for (int c = 0; c < 16; c++) {
        CPA_WAIT(STAGES - 2);
        __syncthreads();
        if (c + STAGES - 1 < 16) load_chunk(c + STAGES - 1);
        CPA_COMMIT();

        const uint32_t sA  = s0 + (uint32_t)(c % STAGES) * SB;
        const uint32_t sBm = sA + TA;

#pragma unroll
        for (int ks = 0; ks < 4; ks++) {
            const int kc = ks * 8 + tig;
            uint32_t ah[2][4];
#pragma unroll
            for (int mt = 0; mt < 2; mt++) {
                const int r = wm + mt * 16 + gid;
                ah[mt][0] = lds32(sA + swz(r,     kc));
                ah[mt][1] = lds32(sA + swz(r + 8, kc));
                ah[mt][2] = lds32(sA + swz(r,     kc + 4));
                ah[mt][3] = lds32(sA + swz(r + 8, kc + 4));
            }
            if (!SPLIT) {
#pragma unroll
                for (int nt = 0; nt < NT; nt++) {
                    const int rn = wn + nt * 8 + gid;
                    const uint32_t b0 = lds32(sBm + swz(rn, kc));
                    const uint32_t b1 = lds32(sBm + swz(rn, kc + 4));
                    MMA_TF32(acc[0][nt], ah[0], b0, b1);
                    MMA_TF32(acc[1][nt], ah[1], b0, b1);
                }
            } else {
                const uint32_t sAl = sA + TA + TB, sBl = sA + 2 * TA + TB;
                uint32_t al[2][4];
#pragma unroll
                for (int mt = 0; mt < 2; mt++) {
                    const int r = wm + mt * 16 + gid;
                    al[mt][0] = lds32(sAl + swz(r,     kc));
                    al[mt][1] = lds32(sAl + swz(r + 8, kc));
                    al[mt][2] = lds32(sAl + swz(r,     kc + 4));
                    al[mt][3] = lds32(sAl + swz(r + 8, kc + 4));
                }
#pragma unroll
                for (int nt = 0; nt < NT; nt++) {
                    const int rn = wn + nt * 8 + gid;
                    const uint32_t bh0 = lds32(sBm + swz(rn, kc));
                    const uint32_t bh1 = lds32(sBm + swz(rn, kc + 4));
                    MMA_TF32(acc[0][nt], ah[0], bh0, bh1);
                    MMA_TF32(acc[1][nt], ah[1], bh0, bh1);
                    MMA_TF32(acc[0][nt], al[0], bh0, bh1);
                    MMA_TF32(acc[1][nt], al[1], bh0, bh1);
                    const uint32_t bl0 = lds32(sBl + swz(rn, kc));
                    const uint32_t bl1 = lds32(sBl + swz(rn, kc + 4));
                    MMA_TF32(acc[0][nt], ah[0], bl0, bl1);
                    MMA_TF32(acc[1][nt], ah[1], bl0, bl1);
                }
            }
        }
    }

    // epilogue
#pragma unroll
    for (int mt = 0; mt < 2; mt++) {
        const size_t r0 = m0 + wm + mt * 16 + gid;
#pragma unroll
        for (int nt = 0; nt < NT; nt++) {
            const size_t cc = n0 + wn + nt * 8 + tig * 2;
            *(float2*)(C + r0 * 512 + cc)       = make_float2(acc[mt][nt][0], acc[mt][nt][1]);
            *(float2*)(C + (r0 + 8) * 512 + cc) = make_float2(acc[mt][nt][2], acc[mt][nt][3]);
        }
    }
}

// ---------------------------------------------------------------------------
// Row softmax over g_attn; output tf32-rounded for GEMM2.
// ---------------------------------------------------------------------------
__global__ void softmax_kernel()
{
    const int row = blockIdx.x;
    const int tid = threadIdx.x;
    float* rp = g_attn + (size_t)row * 512;

    float4 v = *(float4*)(rp + tid * 4);
    float m = fmaxf(fmaxf(v.x, v.y), fmaxf(v.z, v.w));
#pragma unroll
    for (int o = 16; o > 0; o >>= 1) m = fmaxf(m, __shfl_xor_sync(0xFFFFFFFFu, m, o));

    __shared__ float sred[4];
    const int wid = tid >> 5, lane = tid & 31;
    if (lane == 0) sred[wid] = m;
    __syncthreads();
    m = fmaxf(fmaxf(sred[0], sred[1]), fmaxf(sred[2], sred[3]));
    __syncthreads();

    v.x = __expf(v.x - m); v.y = __expf(v.y - m);
    v.z = __expf(v.z - m); v.w = __expf(v.w - m);
    float s = v.x + v.y + v.z + v.w;
#pragma unroll
    for (int o = 16; o > 0; o >>= 1) s += __shfl_xor_sync(0xFFFFFFFFu, s, o);
    if (lane == 0) sred[wid] = s;
    __syncthreads();
    s = sred[0] + sred[1] + sred[2] + sred[3];

    const float inv = 1.0f / s;
    v.x = tf32r(v.x * inv); v.y = tf32r(v.y * inv);
    v.z = tf32r(v.z * inv); v.w = tf32r(v.w * inv);
    *(float4*)(rp + tid * 4) = v;
}

// ---------------------------------------------------------------------------
extern "C" void kernel_launch(void* const* d_in, const int* in_sizes, int n_in,
                              void* d_out, int out_size)
{
    const float* x  = (const float*)d_in[0];
    const float* Wq = (const float*)d_in[1];
    const float* bq = (const float*)d_in[2];
    const float* Wk = (const float*)d_in[3];
    const float* bk = (const float*)d_in[4];
    const float* Wv = (const float*)d_in[5];
    const float* bv = (const float*)d_in[6];
    float* out = (float*)d_out;

    float *pqh, *pql, *pkh, *pkl, *pvT, *pattn;
    cudaGetSymbolAddress((void**)&pqh,  g_qhi);
    cudaGetSymbolAddress((void**)&pql,  g_qlo);
    cudaGetSymbolAddress((void**)&pkh,  g_khi);
    cudaGetSymbolAddress((void**)&pkl,  g_klo);
    cudaGetSymbolAddress((void**)&pvT,  g_vT);
    cudaGetSymbolAddress((void**)&pattn, g_attn);

    const int SMEM_S = 3 * 2 * (16384 + 16384);   // 192 KB (split, BN=128)
    const int SMEM_N = 3 * (16384 + 32768);       // 144 KB (BN=256)
    cudaFuncSetAttribute(gemm_mma<128, true>,  cudaFuncAttributeMaxDynamicSharedMemorySize, SMEM_S);
    cudaFuncSetAttribute(gemm_mma<256, false>, cudaFuncAttributeMaxDynamicSharedMemorySize, SMEM_N);

    // 1) q,k (tf32 hi/lo), vT (tf32)
    qkv_kernel<<<dim3(16, 16, BATCH), 256>>>(x, Wq, bq, Wk, bk, Wv, bv);

    // 2) logits = q k^T per batch (3xTF32)
    gemm_mma<128, true><<<dim3(4, 4, BATCH), 512, SMEM_S>>>(pqh, pql, pkh, pkl, pattn, 0);

    // 3) softmax rows (+ tf32 rounding)
    softmax_kernel<<<BATCH * 512, 128>>>();

    // 4) out = attn @ vT per (b,c), single tf32
    gemm_mma<256, false><<<dim3(2, 4, BATCH * 8), 512, SMEM_N>>>(pattn, pattn, pvT, pvT, out, 3);
}

// round 5
// speedup vs baseline: 1.7107x; 1.7107x over previous
#include <cuda_runtime.h>
#include <cstdint>

#define BATCH 16
#define HW    262144
#define NPIX  4194304

// ---------------- scratch (device globals; no runtime allocation) ----------
__device__ float g_qhi[NPIX], g_qlo[NPIX], g_khi[NPIX], g_klo[NPIX];   // [B,H,W] (w k-permuted)
__device__ float g_vT[BATCH * 8 * HW];                                 // [B,C,W,H] (h k-permuted)
__device__ float g_attn[BATCH * HW];                                   // [B,H,H] (j k-permuted after softmax)

// ---------------- helpers ---------------------------------------------------
__device__ __forceinline__ float tf32r(float x) {
    uint32_t u; asm("cvt.rna.tf32.f32 %0, %1;" : "=r"(u) : "f"(x));
    return __uint_as_float(u);
}
// K-permutation: within each 16-element group, storage pos of col c is 4*(c&3)+((c>>2)&3)
__device__ __forceinline__ int kperm(int k) {
    return (k & ~15) | ((k & 3) << 2) | ((k >> 2) & 3);
}
#define CPA16(s, g)   asm volatile("cp.async.cg.shared.global [%0], [%1], 16;" :: "r"(s), "l"(g) : "memory")
#define CPA_COMMIT()  asm volatile("cp.async.commit_group;" ::: "memory")
#define CPA_WAIT(n)   asm volatile("cp.async.wait_group %0;" :: "n"(n) : "memory")

__device__ __forceinline__ uint32_t smem_u32(const void* p) {
    uint32_t a;
    asm("{ .reg .u64 t; cvta.to.shared.u64 t, %1; cvt.u32.u64 %0, t; }" : "=r"(a) : "l"(p));
    return a;
}
// chunk-level swizzle: row r (128B rows), 16B chunk ch (0..7).
// f(r) flips bit2 between adjacent rows -> LDS.128 phases conflict-free.
__device__ __forceinline__ uint32_t swz128(int r, int ch) {
    const int f = ((r & 1) << 2) | ((r >> 1) & 3);
    return (uint32_t)(r * 128 + ((ch ^ f) << 4));
}
__device__ __forceinline__ uint4 lds128(uint32_t a) {
    uint4 v;
    asm volatile("ld.shared.v4.b32 {%0,%1,%2,%3}, [%4];"
                 : "=r"(v.x), "=r"(v.y), "=r"(v.z), "=r"(v.w) : "r"(a));
    return v;
}
#define MMA4(c, a0, a1, a2, a3, b0, b1) \
    asm volatile("mma.sync.aligned.m16n8k8.row.col.f32.tf32.tf32.f32 " \
                 "{%0,%1,%2,%3},{%4,%5,%6,%7},{%8,%9},{%0,%1,%2,%3};" \
                 : "+f"((c)[0]), "+f"((c)[1]), "+f"((c)[2]), "+f"((c)[3]) \
                 : "r"(a0), "r"(a1), "r"(a2), "r"(a3), "r"(b0), "r"(b1))

// ---------------------------------------------------------------------------
// Fused q/k/v 1x1 convs.  q,k written as tf32 hi/lo pairs with w k-permuted;
// v transposed to [B,C,W,H] (tf32-rounded) with h k-permuted.
// ---------------------------------------------------------------------------
__global__ void __launch_bounds__(256)
qkv_kernel(const float* __restrict__ x,
           const float* __restrict__ Wq, const float* __restrict__ bq,
           const float* __restrict__ Wk, const float* __restrict__ bk,
           const float* __restrict__ Wv, const float* __restrict__ bv)
{
    __shared__ float sWq[8], sWk[8], sWv[64], sBv[8], sB2[2];
    __shared__ float sv[8][32][33];
    const int tid = threadIdx.x;
    if (tid < 8) { sWq[tid] = Wq[tid]; sWk[tid] = Wk[tid]; sBv[tid] = bv[tid]; }
    if (tid >= 8 && tid < 72) sWv[tid - 8] = Wv[tid - 8];
    if (tid == 72) sB2[0] = bq[0];
    if (tid == 73) sB2[1] = bk[0];
    __syncthreads();

    const int b = blockIdx.z, h0 = blockIdx.y * 32, w0 = blockIdx.x * 32;
    const int j = tid & 31, i0 = tid >> 5;

    for (int ii = 0; ii < 4; ii++) {
        const int i = i0 + ii * 8;
        const int h = h0 + i, w = w0 + j;
        const size_t pb = ((size_t)b * 8) * HW + (size_t)h * 512 + w;
        float xv[8];
#pragma unroll
        for (int c = 0; c < 8; c++) xv[c] = x[pb + (size_t)c * HW];

        float q = sB2[0], k = sB2[1];
#pragma unroll
        for (int c = 0; c < 8; c++) { q += xv[c] * sWq[c]; k += xv[c] * sWk[c]; }
        const size_t p = (size_t)b * HW + (size_t)h * 512 + kperm(w);
        const float qh = tf32r(q), kh = tf32r(k);
        g_qhi[p] = qh; g_qlo[p] = tf32r(q - qh);
        g_khi[p] = kh; g_klo[p] = tf32r(k - kh);

#pragma unroll
        for (int o = 0; o < 8; o++) {
            float v = sBv[o];
#pragma unroll
            for (int c = 0; c < 8; c++) v += xv[c] * sWv[o * 8 + c];
            sv[o][i][j] = tf32r(v);
        }
    }
    __syncthreads();

    for (int ii = 0; ii < 4; ii++) {
        const int wl = i0 + ii * 8;   // local w
        const int hl = j;             // local h
#pragma unroll
        for (int c = 0; c < 8; c++) {
            g_vT[(((size_t)b * 8 + c) * 512 + (w0 + wl)) * 512 + kperm(h0 + hl)] = sv[c][hl][wl];
        }
    }
}

// ---------------------------------------------------------------------------
// mma.sync tf32 GEMM: C[m,n] = sum_k A[m,k]*B[n,k], per-z 512x512x512.
// 256 threads, 8 warps (4x2), CTA 128x128, warp tile 32x64, K-chunk 32.
// Operand K-dims are group-16 permuted in GMEM -> LDS.128 fragment loads.
// SPLIT: 3xTF32 using (Ahi,Alo,Bhi,Blo).
// ---------------------------------------------------------------------------
template <int STAGES, bool SPLIT>
__global__ void __launch_bounds__(256)
gemm_mma(const float* __restrict__ Ahi, const float* __restrict__ Alo,
         const float* __restrict__ Bhi, const float* __restrict__ Blo,
         float* __restrict__ Cb, int aShift)
{
    constexpr uint32_t TA = 128 * 32 * 4;                    // 16 KB
    constexpr uint32_t SB = (SPLIT ? 4u : 2u) * TA;          // stage bytes

    extern __shared__ char smem[];
    const uint32_t s0 = smem_u32(smem);

    const int tid  = threadIdx.x;
    const int lane = tid & 31;
    const int wid  = tid >> 5;
    const int wm   = (wid & 3) * 32;      // warp m offset
    const int wn   = (wid >> 2) * 64;     // warp n offset
    const int gid  = lane >> 2;           // fragment group id (0..7)
    const int tig  = lane & 3;            // thread in group  (0..3)

    const int z = blockIdx.z;
    const size_t m0 = (size_t)blockIdx.y * 128;
    const size_t n0 = (size_t)blockIdx.x * 128;
    const float* Ah = Ahi + (size_t)(z >> aShift) * HW;
    const float* Al = Alo + (size_t)(z >> aShift) * HW;
    const float* Bh = Bhi + (size_t)z * HW;
    const float* Bl = Blo + (size_t)z * HW;
    float* C = Cb + (size_t)z * HW;

    // loader mapping: 256 threads -> (seg 0..7 chunks) x (row0 0..31)
    const int seg  = tid & 7;
    const int row0 = tid >> 3;

    auto load_chunk = [&](int c) {
        const uint32_t base = s0 + (uint32_t)(c % STAGES) * SB;
        const size_t go = (size_t)c * 32 + seg * 4;
#pragma unroll
        for (int i = 0; i < 4; i++) {
            const int r = row0 + i * 32;
            const uint32_t sw = swz128(r, seg);
            CPA16(base + sw,      Ah + (m0 + r) * 512 + go);
            CPA16(base + TA + sw, Bh + (n0 + r) * 512 + go);
            if (SPLIT) {
                CPA16(base + 2 * TA + sw, Al + (m0 + r) * 512 + go);
                CPA16(base + 3 * TA + sw, Bl + (n0 + r) * 512 + go);
            }
        }
    };

    float acc[2][8][4] = {};

#pragma unroll
    for (int c = 0; c < STAGES - 1; c++) { load_chunk(c); CPA_COMMIT(); }

    for (int c = 0; c < 16; c++) {
        CPA_WAIT(STAGES - 2);
        __syncthreads();
        if (c + STAGES - 1 < 16) load_chunk(c + STAGES - 1);
        CPA_COMMIT();

        const uint32_t sA  = s0 + (uint32_t)(c % STAGES) * SB;
        const uint32_t sBm = sA + TA;

#pragma unroll
        for (int g = 0; g < 2; g++) {
            const int ch = g * 4 + tig;
            // A fragments: one LDS.128 per 16-row half, covers 2 k-steps
            uint4 aL[2], aH[2];
#pragma unroll
            for (int mt = 0; mt < 2; mt++) {
                aL[mt] = lds128(sA + swz128(wm + mt * 16 + gid,     ch));
                aH[mt] = lds128(sA + swz128(wm + mt * 16 + gid + 8, ch));
            }
            if (!SPLIT) {
#pragma unroll
                for (int nt = 0; nt < 8; nt++) {
                    const uint4 bv = lds128(sBm + swz128(wn + nt * 8 + gid, ch));
#pragma unroll
                    for (int mt = 0; mt < 2; mt++) {
                        MMA4(acc[mt][nt], aL[mt].x, aH[mt].x, aL[mt].y, aH[mt].y, bv.x, bv.y);
                        MMA4(acc[mt][nt], aL[mt].z, aH[mt].z, aL[mt].w, aH[mt].w, bv.z, bv.w);
                    }
                }
            } else {
                const uint32_t sAl = sA + 2 * TA, sBl = sA + 3 * TA;
                uint4 cL[2], cH[2];
#pragma unroll
                for (int mt = 0; mt < 2; mt++) {
                    cL[mt] = lds128(sAl + swz128(wm + mt * 16 + gid,     ch));
                    cH[mt] = lds128(sAl + swz128(wm + mt * 16 + gid + 8, ch));
                }
#pragma unroll
                for (int nt = 0; nt < 8; nt++) {
                    const uint4 bh = lds128(sBm + swz128(wn + nt * 8 + gid, ch));
                    const uint4 bl = lds128(sBl + swz128(wn + nt * 8 + gid, ch));
#pragma unroll
                    for (int mt = 0; mt < 2; mt++) {
                        MMA4(acc[mt][nt], aL[mt].x, aH[mt].x, aL[mt].y, aH[mt].y, bh.x, bh.y);
                        MMA4(acc[mt][nt], cL[mt].x, cH[mt].x, cL[mt].y, cH[mt].y, bh.x, bh.y);
                        MMA4(acc[mt][nt], aL[mt].x, aH[mt].x, aL[mt].y, aH[mt].y, bl.x, bl.y);
                        MMA4(acc[mt][nt], aL[mt].z, aH[mt].z, aL[mt].w, aH[mt].w, bh.z, bh.w);
                        MMA4(acc[mt][nt], cL[mt].z, cH[mt].z, cL[mt].w, cH[mt].w, bh.z, bh.w);
                        MMA4(acc[mt][nt], aL[mt].z, aH[mt].z, aL[mt].w, aH[mt].w, bl.z, bl.w);
                    }
                }
            }
        }
    }

    // epilogue (natural n order)
#pragma unroll
    for (int mt = 0; mt < 2; mt++) {
        const size_t r0 = m0 + wm + mt * 16 + gid;
#pragma unroll
        for (int nt = 0; nt < 8; nt++) {
            const size_t cc = n0 + wn + nt * 8 + tig * 2;
            *(float2*)(C + r0 * 512 + cc)       = make_float2(acc[mt][nt][0], acc[mt][nt][1]);
            *(float2*)(C + (r0 + 8) * 512 + cc) = make_float2(acc[mt][nt][2], acc[mt][nt][3]);
        }
    }
}

// ---------------------------------------------------------------------------
// Row softmax over g_attn; reads natural order, writes k-permuted + tf32.
// ---------------------------------------------------------------------------
__global__ void softmax_kernel()
{
    const int row = blockIdx.x;
    const int tid = threadIdx.x;
    float* rp = g_attn + (size_t)row * 512;

    float4 v = *(float4*)(rp + tid * 4);
    float m = fmaxf(fmaxf(v.x, v.y), fmaxf(v.z, v.w));
#pragma unroll
    for (int o = 16; o > 0; o >>= 1) m = fmaxf(m, __shfl_xor_sync(0xFFFFFFFFu, m, o));

    __shared__ float sred[4];
    const int wid = tid >> 5, lane = tid & 31;
    if (lane == 0) sred[wid] = m;
    __syncthreads();
    m = fmaxf(fmaxf(sred[0], sred[1]), fmaxf(sred[2], sred[3]));
    __syncthreads();

    v.x = __expf(v.x - m); v.y = __expf(v.y - m);
    v.z = __expf(v.z - m); v.w = __expf(v.w - m);
    float s = v.x + v.y + v.z + v.w;
#pragma unroll
    for (int o = 16; o > 0; o >>= 1) s += __shfl_xor_sync(0xFFFFFFFFu, s, o);
    if (lane == 0) sred[wid] = s;
    __syncthreads();
    s = sred[0] + sred[1] + sred[2] + sred[3];

    const float inv = 1.0f / s;
    // cols c = 16G + 4u + i  ->  permuted pos = 16G + 4i + u
    const int G = tid >> 2, u = tid & 3;
    float* gp = rp + G * 16 + u;
    __syncthreads();                       // everyone finished reading the row
    gp[0]  = tf32r(v.x * inv);
    gp[4]  = tf32r(v.y * inv);
    gp[8]  = tf32r(v.z * inv);
    gp[12] = tf32r(v.w * inv);
}

// ---------------------------------------------------------------------------
extern "C" void kernel_launch(void* const* d_in, const int* in_sizes, int n_in,
                              void* d_out, int out_size)
{
    const float* x  = (const float*)d_in[0];
    const float* Wq = (const float*)d_in[1];
    const float* bq = (const float*)d_in[2];
    const float* Wk = (const float*)d_in[3];
    const float* bk = (const float*)d_in[4];
    const float* Wv = (const float*)d_in[5];
    const float* bv = (const float*)d_in[6];
    float* out = (float*)d_out;

    float *pqh, *pql, *pkh, *pkl, *pvT, *pattn;
    cudaGetSymbolAddress((void**)&pqh,  g_qhi);
    cudaGetSymbolAddress((void**)&pql,  g_qlo);
    cudaGetSymbolAddress((void**)&pkh,  g_khi);
    cudaGetSymbolAddress((void**)&pkl,  g_klo);
    cudaGetSymbolAddress((void**)&pvT,  g_vT);
    cudaGetSymbolAddress((void**)&pattn, g_attn);

    const int SMEM_S = 3 * 4 * 16384;   // 192 KB (split, 3 stages)
    const int SMEM_N = 4 * 2 * 16384;   // 128 KB (4 stages)
    cudaFuncSetAttribute(gemm_mma<3, true>,  cudaFuncAttributeMaxDynamicSharedMemorySize, SMEM_S);
    cudaFuncSetAttribute(gemm_mma<4, false>, cudaFuncAttributeMaxDynamicSharedMemorySize, SMEM_N);

    // 1) q,k (tf32 hi/lo, w-permuted), vT (tf32, h-permuted)
    qkv_kernel<<<dim3(16, 16, BATCH), 256>>>(x, Wq, bq, Wk, bk, Wv, bv);

    // 2) logits = q k^T per batch (3xTF32)
    gemm_mma<3, true><<<dim3(4, 4, BATCH), 256, SMEM_S>>>(pqh, pql, pkh, pkl, pattn, 0);

    // 3) softmax rows (+ tf32 rounding + j-permutation)
    softmax_kernel<<<BATCH * 512, 128>>>();

    // 4) out = attn @ vT per (b,c), single tf32
    gemm_mma<4, false><<<dim3(4, 4, BATCH * 8), 256, SMEM_N>>>(pattn, pattn, pvT, pvT, out, 3);
}

// round 6
// speedup vs baseline: 1.7683x; 1.0337x over previous
#include <cuda_runtime.h>
#include <cstdint>

#define BATCH 16
#define HW    262144
#define NPIX  4194304

// ---------------- scratch (device globals; no runtime allocation) ----------
__device__ float g_qhi[NPIX], g_qlo[NPIX], g_khi[NPIX], g_klo[NPIX];   // [B,H,W] (w k-permuted)
__device__ float g_vT[BATCH * 8 * HW];                                 // [B,C,W,H] (h k-permuted)
__device__ float g_attn[BATCH * HW];                                   // [B,H,H] (j k-permuted after softmax)

// ---------------- helpers ---------------------------------------------------
__device__ __forceinline__ float tf32r(float x) {
    uint32_t u; asm("cvt.rna.tf32.f32 %0, %1;" : "=r"(u) : "f"(x));
    return __uint_as_float(u);
}
// K-permutation: within each 16-element group, storage pos of col c is 4*(c&3)+((c>>2)&3)
__device__ __forceinline__ int kperm(int k) {
    return (k & ~15) | ((k & 3) << 2) | ((k >> 2) & 3);
}
#define CPA16(s, g)   asm volatile("cp.async.cg.shared.global [%0], [%1], 16;" :: "r"(s), "l"(g) : "memory")
#define CPA_COMMIT()  asm volatile("cp.async.commit_group;" ::: "memory")
#define CPA_WAIT(n)   asm volatile("cp.async.wait_group %0;" :: "n"(n) : "memory")

__device__ __forceinline__ uint32_t smem_u32(const void* p) {
    uint32_t a;
    asm("{ .reg .u64 t; cvta.to.shared.u64 t, %1; cvt.u32.u64 %0, t; }" : "=r"(a) : "l"(p));
    return a;
}
// chunk-level swizzle: row r (128B rows), 16B chunk ch (0..7).
// f(r) flips bit2 between adjacent rows -> LDS.128 phases conflict-free.
__device__ __forceinline__ uint32_t swz128(int r, int ch) {
    const int f = ((r & 1) << 2) | ((r >> 1) & 3);
    return (uint32_t)(r * 128 + ((ch ^ f) << 4));
}
__device__ __forceinline__ uint4 lds128(uint32_t a) {
    uint4 v;
    asm volatile("ld.shared.v4.b32 {%0,%1,%2,%3}, [%4];"
                 : "=r"(v.x), "=r"(v.y), "=r"(v.z), "=r"(v.w) : "r"(a));
    return v;
}
#define MMA4(c, a0, a1, a2, a3, b0, b1) \
    asm volatile("mma.sync.aligned.m16n8k8.row.col.f32.tf32.tf32.f32 " \
                 "{%0,%1,%2,%3},{%4,%5,%6,%7},{%8,%9},{%0,%1,%2,%3};" \
                 : "+f"((c)[0]), "+f"((c)[1]), "+f"((c)[2]), "+f"((c)[3]) \
                 : "r"(a0), "r"(a1), "r"(a2), "r"(a3), "r"(b0), "r"(b1))

// ---------------------------------------------------------------------------
// Fused q/k/v 1x1 convs.  q,k written as tf32 hi/lo pairs with w k-permuted;
// v transposed to [B,C,W,H] (tf32-rounded) with h k-permuted.
// ---------------------------------------------------------------------------
__global__ void __launch_bounds__(256)
qkv_kernel(const float* __restrict__ x,
           const float* __restrict__ Wq, const float* __restrict__ bq,
           const float* __restrict__ Wk, const float* __restrict__ bk,
           const float* __restrict__ Wv, const float* __restrict__ bv)
{
    __shared__ float sWq[8], sWk[8], sWv[64], sBv[8], sB2[2];
    __shared__ float sv[8][32][33];
    const int tid = threadIdx.x;
    if (tid < 8) { sWq[tid] = Wq[tid]; sWk[tid] = Wk[tid]; sBv[tid] = bv[tid]; }
    if (tid >= 8 && tid < 72) sWv[tid - 8] = Wv[tid - 8];
    if (tid == 72) sB2[0] = bq[0];
    if (tid == 73) sB2[1] = bk[0];
    __syncthreads();

    const int b = blockIdx.z, h0 = blockIdx.y * 32, w0 = blockIdx.x * 32;
    const int j = tid & 31, i0 = tid >> 5;

    for (int ii = 0; ii < 4; ii++) {
        const int i = i0 + ii * 8;
        const int h = h0 + i, w = w0 + j;
        const size_t pb = ((size_t)b * 8) * HW + (size_t)h * 512 + w;
        float xv[8];
#pragma unroll
        for (int c = 0; c < 8; c++) xv[c] = x[pb + (size_t)c * HW];

        float q = sB2[0], k = sB2[1];
#pragma unroll
        for (int c = 0; c < 8; c++) { q += xv[c] * sWq[c]; k += xv[c] * sWk[c]; }
        const size_t p = (size_t)b * HW + (size_t)h * 512 + kperm(w);
        const float qh = tf32r(q), kh = tf32r(k);
        g_qhi[p] = qh; g_qlo[p] = tf32r(q - qh);
        g_khi[p] = kh; g_klo[p] = tf32r(k - kh);

#pragma unroll
        for (int o = 0; o < 8; o++) {
            float v = sBv[o];
#pragma unroll
            for (int c = 0; c < 8; c++) v += xv[c] * sWv[o * 8 + c];
            sv[o][i][j] = tf32r(v);
        }
    }
    __syncthreads();

    for (int ii = 0; ii < 4; ii++) {
        const int wl = i0 + ii * 8;   // local w
        const int hl = j;             // local h
#pragma unroll
        for (int c = 0; c < 8; c++) {
            g_vT[(((size_t)b * 8 + c) * 512 + (w0 + wl)) * 512 + kperm(h0 + hl)] = sv[c][hl][wl];
        }
    }
}

// ---------------------------------------------------------------------------
// mma.sync tf32 GEMM: C[m,n] = sum_k A[m,k]*B[n,k], per-z 512x512x512.
// 256 threads, 8 warps (4x2), CTA 128x128, warp tile 32x64, K-chunk 32.
// Operand K-dims are group-16 permuted in GMEM -> LDS.128 fragment loads.
// All swizzled SMEM offsets are hoisted into registers before the K loop.
// SPLIT: 3xTF32 using (Ahi,Alo,Bhi,Blo).
// ---------------------------------------------------------------------------
template <int STAGES, bool SPLIT>
__global__ void __launch_bounds__(256)
gemm_mma(const float* __restrict__ Ahi, const float* __restrict__ Alo,
         const float* __restrict__ Bhi, const float* __restrict__ Blo,
         float* __restrict__ Cb, int aShift)
{
    constexpr uint32_t TA = 128 * 32 * 4;                    // 16 KB
    constexpr uint32_t SB = (SPLIT ? 4u : 2u) * TA;          // stage bytes

    extern __shared__ char smem[];
    const uint32_t s0 = smem_u32(smem);

    const int tid  = threadIdx.x;
    const int lane = tid & 31;
    const int wid  = tid >> 5;
    const int wm   = (wid & 3) * 32;      // warp m offset
    const int wn   = (wid >> 2) * 64;     // warp n offset
    const int gid  = lane >> 2;           // fragment group id (0..7)
    const int tig  = lane & 3;            // thread in group  (0..3)

    const int z = blockIdx.z;
    const size_t m0 = (size_t)blockIdx.y * 128;
    const size_t n0 = (size_t)blockIdx.x * 128;
    const float* Ah = Ahi + (size_t)(z >> aShift) * HW;
    const float* Al = Alo + (size_t)(z >> aShift) * HW;
    const float* Bh = Bhi + (size_t)z * HW;
    const float* Bl = Blo + (size_t)z * HW;
    float* C = Cb + (size_t)z * HW;

    // ---- hoisted swizzled offsets (loop-invariant) ----
    uint32_t oA[2][2][2];       // [g][mt][half]   (A tile, base-relative)
    uint32_t oB[2][8];          // [g][nt]         (B tile, includes +TA)
#pragma unroll
    for (int g = 0; g < 2; g++) {
        const int ch = g * 4 + tig;
#pragma unroll
        for (int mt = 0; mt < 2; mt++) {
            oA[g][mt][0] = swz128(wm + mt * 16 + gid,     ch);
            oA[g][mt][1] = swz128(wm + mt * 16 + gid + 8, ch);
        }
#pragma unroll
        for (int nt = 0; nt < 8; nt++)
            oB[g][nt] = TA + swz128(wn + nt * 8 + gid, ch);
    }

    // loader mapping: 256 threads -> (seg 0..7 chunks) x (row0 0..31)
    const int seg  = tid & 7;
    const int row0 = tid >> 3;
    uint32_t lsw[4];
#pragma unroll
    for (int i = 0; i < 4; i++) lsw[i] = swz128(row0 + i * 32, seg);
    const size_t grow = (size_t)row0 * 512 + seg * 4;   // row0-th row, seg-th 4-float group

    auto load_chunk = [&](int c, uint32_t base) {
        const size_t go = grow + (size_t)c * 32;
#pragma unroll
        for (int i = 0; i < 4; i++) {
            const uint32_t sw = lsw[i];
            const size_t g2 = go + (size_t)i * 32 * 512;
            CPA16(base + sw,      Ah + m0 * 512 + g2);
            CPA16(base + TA + sw, Bh + n0 * 512 + g2);
            if (SPLIT) {
                CPA16(base + 2 * TA + sw, Al + m0 * 512 + g2);
                CPA16(base + 3 * TA + sw, Bl + n0 * 512 + g2);
            }
        }
    };

    float acc[2][8][4] = {};

    uint32_t stW = s0;               // write-stage base
    uint32_t stR = s0;               // read-stage base
#pragma unroll
    for (int c = 0; c < STAGES - 1; c++) {
        load_chunk(c, stW); CPA_COMMIT();
        stW += SB; if (stW == s0 + STAGES * SB) stW = s0;
    }

    for (int c = 0; c < 16; c++) {
        CPA_WAIT(STAGES - 2);
        __syncthreads();
        if (c + STAGES - 1 < 16) load_chunk(c + STAGES - 1, stW);
        CPA_COMMIT();
        stW += SB; if (stW == s0 + STAGES * SB) stW = s0;

        const uint32_t sA = stR;
        stR += SB; if (stR == s0 + STAGES * SB) stR = s0;

#pragma unroll
        for (int g = 0; g < 2; g++) {
            uint4 aL[2], aH[2];
#pragma unroll
            for (int mt = 0; mt < 2; mt++) {
                aL[mt] = lds128(sA + oA[g][mt][0]);
                aH[mt] = lds128(sA + oA[g][mt][1]);
            }
            if (!SPLIT) {
#pragma unroll
                for (int nt = 0; nt < 8; nt++) {
                    const uint4 bv = lds128(sA + oB[g][nt]);
#pragma unroll
                    for (int mt = 0; mt < 2; mt++) {
                        MMA4(acc[mt][nt], aL[mt].x, aH[mt].x, aL[mt].y, aH[mt].y, bv.x, bv.y);
                        MMA4(acc[mt][nt], aL[mt].z, aH[mt].z, aL[mt].w, aH[mt].w, bv.z, bv.w);
                    }
                }
            } else {
                uint4 cL[2], cH[2];
#pragma unroll
                for (int mt = 0; mt < 2; mt++) {
                    cL[mt] = lds128(sA + 2 * TA + oA[g][mt][0]);
                    cH[mt] = lds128(sA + 2 * TA + oA[g][mt][1]);
                }
#pragma unroll
                for (int nt = 0; nt < 8; nt++) {
                    const uint4 bh = lds128(sA + oB[g][nt]);
                    const uint4 bl = lds128(sA + 2 * TA + oB[g][nt]);
#pragma unroll
                    for (int mt = 0; mt < 2; mt++) {
                        MMA4(acc[mt][nt], aL[mt].x, aH[mt].x, aL[mt].y, aH[mt].y, bh.x, bh.y);
                        MMA4(acc[mt][nt], cL[mt].x, cH[mt].x, cL[mt].y, cH[mt].y, bh.x, bh.y);
                        MMA4(acc[mt][nt], aL[mt].x, aH[mt].x, aL[mt].y, aH[mt].y, bl.x, bl.y);
                        MMA4(acc[mt][nt], aL[mt].z, aH[mt].z, aL[mt].w, aH[mt].w, bh.z, bh.w);
                        MMA4(acc[mt][nt], cL[mt].z, cH[mt].z, cL[mt].w, cH[mt].w, bh.z, bh.w);
                        MMA4(acc[mt][nt], aL[mt].z, aH[mt].z, aL[mt].w, aH[mt].w, bl.z, bl.w);
                    }
                }
            }
        }
    }

    // epilogue (natural n order)
#pragma unroll
    for (int mt = 0; mt < 2; mt++) {
        const size_t r0 = m0 + wm + mt * 16 + gid;
#pragma unroll
        for (int nt = 0; nt < 8; nt++) {
            const size_t cc = n0 + wn + nt * 8 + tig * 2;
            *(float2*)(C + r0 * 512 + cc)       = make_float2(acc[mt][nt][0], acc[mt][nt][1]);
            *(float2*)(C + (r0 + 8) * 512 + cc) = make_float2(acc[mt][nt][2], acc[mt][nt][3]);
        }
    }
}

// ---------------------------------------------------------------------------
// Row softmax over g_attn; reads natural order, writes k-permuted + tf32.
// ---------------------------------------------------------------------------
__global__ void softmax_kernel()
{
    const int row = blockIdx.x;
    const int tid = threadIdx.x;
    float* rp = g_attn + (size_t)row * 512;

    float4 v = *(float4*)(rp + tid * 4);
    float m = fmaxf(fmaxf(v.x, v.y), fmaxf(v.z, v.w));
#pragma unroll
    for (int o = 16; o > 0; o >>= 1) m = fmaxf(m, __shfl_xor_sync(0xFFFFFFFFu, m, o));

    __shared__ float sred[4];
    const int wid = tid >> 5, lane = tid & 31;
    if (lane == 0) sred[wid] = m;
    __syncthreads();
    m = fmaxf(fmaxf(sred[0], sred[1]), fmaxf(sred[2], sred[3]));
    __syncthreads();

    v.x = __expf(v.x - m); v.y = __expf(v.y - m);
    v.z = __expf(v.z - m); v.w = __expf(v.w - m);
    float s = v.x + v.y + v.z + v.w;
#pragma unroll
    for (int o = 16; o > 0; o >>= 1) s += __shfl_xor_sync(0xFFFFFFFFu, s, o);
    if (lane == 0) sred[wid] = s;
    __syncthreads();
    s = sred[0] + sred[1] + sred[2] + sred[3];

    const float inv = 1.0f / s;
    // cols c = 16G + 4u + i  ->  permuted pos = 16G + 4i + u
    const int G = tid >> 2, u = tid & 3;
    float* gp = rp + G * 16 + u;
    __syncthreads();                       // everyone finished reading the row
    gp[0]  = tf32r(v.x * inv);
    gp[4]  = tf32r(v.y * inv);
    gp[8]  = tf32r(v.z * inv);
    gp[12] = tf32r(v.w * inv);
}

// ---------------------------------------------------------------------------
extern "C" void kernel_launch(void* const* d_in, const int* in_sizes, int n_in,
                              void* d_out, int out_size)
{
    const float* x  = (const float*)d_in[0];
    const float* Wq = (const float*)d_in[1];
    const float* bq = (const float*)d_in[2];
    const float* Wk = (const float*)d_in[3];
    const float* bk = (const float*)d_in[4];
    const float* Wv = (const float*)d_in[5];
    const float* bv = (const float*)d_in[6];
    float* out = (float*)d_out;

    float *pqh, *pql, *pkh, *pkl, *pvT, *pattn;
    cudaGetSymbolAddress((void**)&pqh,  g_qhi);
    cudaGetSymbolAddress((void**)&pql,  g_qlo);
    cudaGetSymbolAddress((void**)&pkh,  g_khi);
    cudaGetSymbolAddress((void**)&pkl,  g_klo);
    cudaGetSymbolAddress((void**)&pvT,  g_vT);
    cudaGetSymbolAddress((void**)&pattn, g_attn);

    const int SMEM_S = 3 * 4 * 16384;   // 192 KB (split, 3 stages)
    const int SMEM_N = 4 * 2 * 16384;   // 128 KB (4 stages)
    cudaFuncSetAttribute(gemm_mma<3, true>,  cudaFuncAttributeMaxDynamicSharedMemorySize, SMEM_S);
    cudaFuncSetAttribute(gemm_mma<4, false>, cudaFuncAttributeMaxDynamicSharedMemorySize, SMEM_N);

    // 1) q,k (tf32 hi/lo, w-permuted), vT (tf32, h-permuted)
    qkv_kernel<<<dim3(16, 16, BATCH), 256>>>(x, Wq, bq, Wk, bk, Wv, bv);

    // 2) logits = q k^T per batch (3xTF32)
    gemm_mma<3, true><<<dim3(4, 4, BATCH), 256, SMEM_S>>>(pqh, pql, pkh, pkl, pattn, 0);

    // 3) softmax rows (+ tf32 rounding + j-permutation)
    softmax_kernel<<<BATCH * 512, 128>>>();

    // 4) out = attn @ vT per (b,c), single tf32
    gemm_mma<4, false><<<dim3(4, 4, BATCH * 8), 256, SMEM_N>>>(pattn, pattn, pvT, pvT, out, 3);
}

// round 7
// speedup vs baseline: 1.9197x; 1.0856x over previous
#include <cuda_runtime.h>
#include <cstdint>

#define BATCH 16
#define HW    262144
#define NPIX  4194304

// ---------------- scratch (device globals; no runtime allocation) ----------
// q,k packed rows: per (b,h), 1024 floats = 32 groups x (16 hi | 16 lo), k-permuted
__device__ float g_qp[NPIX * 2], g_kp[NPIX * 2];
__device__ float g_vT[BATCH * 8 * HW];      // [B,C,W,H] (h k-permuted)
__device__ float g_attn[BATCH * HW];        // [B,H,H] (j k-permuted after softmax)

// ---------------- helpers ---------------------------------------------------
__device__ __forceinline__ float tf32r(float x) {
    uint32_t u; asm("cvt.rna.tf32.f32 %0, %1;" : "=r"(u) : "f"(x));
    return __uint_as_float(u);
}
// within a 16-group: storage pos of col c is 4*(c&3)+((c>>2)&3)
__device__ __forceinline__ int kperm(int k) {
    return (k & ~15) | ((k & 3) << 2) | ((k >> 2) & 3);
}
#define CPA16(s, g)   asm volatile("cp.async.cg.shared.global [%0], [%1], 16;" :: "r"(s), "l"(g) : "memory")
#define CPA_COMMIT()  asm volatile("cp.async.commit_group;" ::: "memory")
#define CPA_WAIT(n)   asm volatile("cp.async.wait_group %0;" :: "n"(n) : "memory")

__device__ __forceinline__ uint32_t smem_u32(const void* p) {
    uint32_t a;
    asm("{ .reg .u64 t; cvta.to.shared.u64 t, %1; cvt.u32.u64 %0, t; }" : "=r"(a) : "l"(p));
    return a;
}
// chunk-level swizzle: row r (128B rows), 16B chunk ch (0..7).
__device__ __forceinline__ uint32_t swz128(int r, int ch) {
    const int f = ((r & 1) << 2) | ((r >> 1) & 3);
    return (uint32_t)(r * 128 + ((ch ^ f) << 4));
}
__device__ __forceinline__ uint4 lds128(uint32_t a) {
    uint4 v;
    asm volatile("ld.shared.v4.b32 {%0,%1,%2,%3}, [%4];"
                 : "=r"(v.x), "=r"(v.y), "=r"(v.z), "=r"(v.w) : "r"(a));
    return v;
}
#define MMA4(c, a0, a1, a2, a3, b0, b1) \
    asm volatile("mma.sync.aligned.m16n8k8.row.col.f32.tf32.tf32.f32 " \
                 "{%0,%1,%2,%3},{%4,%5,%6,%7},{%8,%9},{%0,%1,%2,%3};" \
                 : "+f"((c)[0]), "+f"((c)[1]), "+f"((c)[2]), "+f"((c)[3]) \
                 : "r"(a0), "r"(a1), "r"(a2), "r"(a3), "r"(b0), "r"(b1))

// ---------------------------------------------------------------------------
// Fused q/k/v 1x1 convs.  q,k written as packed hi/lo tf32 rows (1024 wide,
// k-permuted); v transposed to [B,C,W,H] (tf32, h k-permuted).
// ---------------------------------------------------------------------------
__global__ void __launch_bounds__(256)
qkv_kernel(const float* __restrict__ x,
           const float* __restrict__ Wq, const float* __restrict__ bq,
           const float* __restrict__ Wk, const float* __restrict__ bk,
           const float* __restrict__ Wv, const float* __restrict__ bv)
{
    __shared__ float sWq[8], sWk[8], sWv[64], sBv[8], sB2[2];
    __shared__ float sv[8][32][33];
    const int tid = threadIdx.x;
    if (tid < 8) { sWq[tid] = Wq[tid]; sWk[tid] = Wk[tid]; sBv[tid] = bv[tid]; }
    if (tid >= 8 && tid < 72) sWv[tid - 8] = Wv[tid - 8];
    if (tid == 72) sB2[0] = bq[0];
    if (tid == 73) sB2[1] = bk[0];
    __syncthreads();

    const int b = blockIdx.z, h0 = blockIdx.y * 32, w0 = blockIdx.x * 32;
    const int j = tid & 31, i0 = tid >> 5;

    for (int ii = 0; ii < 4; ii++) {
        const int i = i0 + ii * 8;
        const int h = h0 + i, w = w0 + j;
        const size_t pb = ((size_t)b * 8) * HW + (size_t)h * 512 + w;
        float xv[8];
#pragma unroll
        for (int c = 0; c < 8; c++) xv[c] = x[pb + (size_t)c * HW];

        float q = sB2[0], k = sB2[1];
#pragma unroll
        for (int c = 0; c < 8; c++) { q += xv[c] * sWq[c]; k += xv[c] * sWk[c]; }
        // packed row: group g = w>>4 (32 floats), pos = perm(w)&15; hi at +0, lo at +16
        const int grp = w >> 4, pos = ((w & 3) << 2) | ((w >> 2) & 3);
        const size_t p = ((size_t)b * 512 + h) * 1024 + grp * 32 + pos;
        const float qh = tf32r(q), kh = tf32r(k);
        g_qp[p] = qh; g_qp[p + 16] = tf32r(q - qh);
        g_kp[p] = kh; g_kp[p + 16] = tf32r(k - kh);

#pragma unroll
        for (int o = 0; o < 8; o++) {
            float v = sBv[o];
#pragma unroll
            for (int c = 0; c < 8; c++) v += xv[c] * sWv[o * 8 + c];
            sv[o][i][j] = tf32r(v);
        }
    }
    __syncthreads();

    for (int ii = 0; ii < 4; ii++) {
        const int wl = i0 + ii * 8;   // local w
        const int hl = j;             // local h
#pragma unroll
        for (int c = 0; c < 8; c++) {
            g_vT[(((size_t)b * 8 + c) * 512 + (w0 + wl)) * 512 + kperm(h0 + hl)] = sv[c][hl][wl];
        }
    }
}

// ---------------------------------------------------------------------------
// mma.sync tf32 GEMM: C[m,n] = sum_k A[m,k]*B[n,k], per-z 512x512x512.
// 256 threads, 8 warps (4x2), CTA 128x128, warp tile 32x64.
// 3-stage cp.async pipeline, 32KB/stage -> 96KB total -> 2 CTAs/SM.
//   SPLIT=false: rows 512 wide, 16 chunks of 32 k.
//   SPLIT=true : packed hi/lo rows 1024 wide, 32 chunks of 16 k, 3xTF32.
// ---------------------------------------------------------------------------
template <bool SPLIT>
__global__ void __launch_bounds__(256, 2)
gemm_mma(const float* __restrict__ Ab, const float* __restrict__ Bb,
         float* __restrict__ Cb, int aShift)
{
    constexpr int ROWLEN = SPLIT ? 1024 : 512;    // floats per operand row
    constexpr int NCH    = SPLIT ? 32 : 16;       // chunks (128B per row each)
    constexpr int STAGES = 3;
    constexpr uint32_t TA = 128 * 32 * 4;         // 16 KB per tile
    constexpr uint32_t SB = 2 * TA;               // 32 KB per stage

    extern __shared__ char smem[];
    const uint32_t s0 = smem_u32(smem);

    const int tid  = threadIdx.x;
    const int lane = tid & 31;
    const int wid  = tid >> 5;
    const int wm   = (wid & 3) * 32;
    const int wn   = (wid >> 2) * 64;
    const int gid  = lane >> 2;
    const int tig  = lane & 3;

    const int z = blockIdx.z;
    const size_t m0 = (size_t)blockIdx.y * 128;
    const size_t n0 = (size_t)blockIdx.x * 128;
    const float* A = Ab + (size_t)(z >> aShift) * 512 * ROWLEN;
    const float* B = Bb + (size_t)z * 512 * ROWLEN;
    float* C = Cb + (size_t)z * HW;

    // ---- hoisted swizzled offsets ----
    uint32_t oA[2][2][2];   // [sel][mt][half]  sel: chunk tig / 4+tig
    uint32_t oB[2][8];      // [sel][nt] (+TA)
#pragma unroll
    for (int s = 0; s < 2; s++) {
        const int ch = s * 4 + tig;
#pragma unroll
        for (int mt = 0; mt < 2; mt++) {
            oA[s][mt][0] = swz128(wm + mt * 16 + gid,     ch);
            oA[s][mt][1] = swz128(wm + mt * 16 + gid + 8, ch);
        }
#pragma unroll
        for (int nt = 0; nt < 8; nt++)
            oB[s][nt] = TA + swz128(wn + nt * 8 + gid, ch);
    }

    // loader: 256 threads -> (seg 0..7) x (row0 0..31), 4 rows each per tile
    const int seg  = tid & 7;
    const int row0 = tid >> 3;
    uint32_t lsw[4];
#pragma unroll
    for (int i = 0; i < 4; i++) lsw[i] = swz128(row0 + i * 32, seg);
    const size_t grow = (size_t)row0 * ROWLEN + seg * 4;

    auto load_chunk = [&](int c, uint32_t base) {
        const size_t go = grow + (size_t)c * 32;
#pragma unroll
        for (int i = 0; i < 4; i++) {
            const size_t g2 = go + (size_t)i * 32 * ROWLEN;
            CPA16(base + lsw[i],      A + m0 * ROWLEN + g2);
            CPA16(base + TA + lsw[i], B + n0 * ROWLEN + g2);
        }
    };

    float acc[2][8][4] = {};

    uint32_t stW = s0, stR = s0;
#pragma unroll
    for (int c = 0; c < STAGES - 1; c++) {
        load_chunk(c, stW); CPA_COMMIT();
        stW += SB; if (stW == s0 + STAGES * SB) stW = s0;
    }

    for (int c = 0; c < NCH; c++) {
        CPA_WAIT(STAGES - 2);
        __syncthreads();
        if (c + STAGES - 1 < NCH) load_chunk(c + STAGES - 1, stW);
        CPA_COMMIT();
        stW += SB; if (stW == s0 + STAGES * SB) stW = s0;

        const uint32_t sA = stR;
        stR += SB; if (stR == s0 + STAGES * SB) stR = s0;

        if (!SPLIT) {
#pragma unroll
            for (int g = 0; g < 2; g++) {
                uint4 aL[2], aH[2];
#pragma unroll
                for (int mt = 0; mt < 2; mt++) {
                    aL[mt] = lds128(sA + oA[g][mt][0]);
                    aH[mt] = lds128(sA + oA[g][mt][1]);
                }
#pragma unroll
                for (int nt = 0; nt < 8; nt++) {
                    const uint4 bv = lds128(sA + oB[g][nt]);
#pragma unroll
                    for (int mt = 0; mt < 2; mt++) {
                        MMA4(acc[mt][nt], aL[mt].x, aH[mt].x, aL[mt].y, aH[mt].y, bv.x, bv.y);
                        MMA4(acc[mt][nt], aL[mt].z, aH[mt].z, aL[mt].w, aH[mt].w, bv.z, bv.w);
                    }
                }
            }
        } else {
            // one 16-k group: hi = chunks 0-3 (sel 0), lo = chunks 4-7 (sel 1)
            uint4 ahL[2], ahH[2], alL[2], alH[2];
#pragma unroll
            for (int mt = 0; mt < 2; mt++) {
                ahL[mt] = lds128(sA + oA[0][mt][0]);
                ahH[mt] = lds128(sA + oA[0][mt][1]);
                alL[mt] = lds128(sA + oA[1][mt][0]);
                alH[mt] = lds128(sA + oA[1][mt][1]);
            }
#pragma unroll
            for (int nt = 0; nt < 8; nt++) {
                const uint4 bh = lds128(sA + oB[0][nt]);
                const uint4 bl = lds128(sA + oB[1][nt]);
#pragma unroll
                for (int mt = 0; mt < 2; mt++) {
                    MMA4(acc[mt][nt], ahL[mt].x, ahH[mt].x, ahL[mt].y, ahH[mt].y, bh.x, bh.y);
                    MMA4(acc[mt][nt], alL[mt].x, alH[mt].x, alL[mt].y, alH[mt].y, bh.x, bh.y);
                    MMA4(acc[mt][nt], ahL[mt].x, ahH[mt].x, ahL[mt].y, ahH[mt].y, bl.x, bl.y);
                    MMA4(acc[mt][nt], ahL[mt].z, ahH[mt].z, ahL[mt].w, ahH[mt].w, bh.z, bh.w);
                    MMA4(acc[mt][nt], alL[mt].z, alH[mt].z, alL[mt].w, alH[mt].w, bh.z, bh.w);
                    MMA4(acc[mt][nt], ahL[mt].z, ahH[mt].z, ahL[mt].w, ahH[mt].w, bl.z, bl.w);
                }
            }
        }
    }

    // epilogue (natural n order)
#pragma unroll
    for (int mt = 0; mt < 2; mt++) {
        const size_t r0 = m0 + wm + mt * 16 + gid;
#pragma unroll
        for (int nt = 0; nt < 8; nt++) {
            const size_t cc = n0 + wn + nt * 8 + tig * 2;
            *(float2*)(C + r0 * 512 + cc)       = make_float2(acc[mt][nt][0], acc[mt][nt][1]);
            *(float2*)(C + (r0 + 8) * 512 + cc) = make_float2(acc[mt][nt][2], acc[mt][nt][3]);
        }
    }
}

// ---------------------------------------------------------------------------
// Row softmax over g_attn; reads natural order, writes k-permuted + tf32.
// ---------------------------------------------------------------------------
__global__ void softmax_kernel()
{
    const int row = blockIdx.x;
    const int tid = threadIdx.x;
    float* rp = g_attn + (size_t)row * 512;

    float4 v = *(float4*)(rp + tid * 4);
    float m = fmaxf(fmaxf(v.x, v.y), fmaxf(v.z, v.w));
#pragma unroll
    for (int o = 16; o > 0; o >>= 1) m = fmaxf(m, __shfl_xor_sync(0xFFFFFFFFu, m, o));

    __shared__ float sred[4];
    const int wid = tid >> 5, lane = tid & 31;
    if (lane == 0) sred[wid] = m;
    __syncthreads();
    m = fmaxf(fmaxf(sred[0], sred[1]), fmaxf(sred[2], sred[3]));
    __syncthreads();

    v.x = __expf(v.x - m); v.y = __expf(v.y - m);
    v.z = __expf(v.z - m); v.w = __expf(v.w - m);
    float s = v.x + v.y + v.z + v.w;
#pragma unroll
    for (int o = 16; o > 0; o >>= 1) s += __shfl_xor_sync(0xFFFFFFFFu, s, o);
    if (lane == 0) sred[wid] = s;
    __syncthreads();
    s = sred[0] + sred[1] + sred[2] + sred[3];

    const float inv = 1.0f / s;
    const int G = tid >> 2, u = tid & 3;
    float* gp = rp + G * 16 + u;
    __syncthreads();
    gp[0]  = tf32r(v.x * inv);
    gp[4]  = tf32r(v.y * inv);
    gp[8]  = tf32r(v.z * inv);
    gp[12] = tf32r(v.w * inv);
}

// ---------------------------------------------------------------------------
extern "C" void kernel_launch(void* const* d_in, const int* in_sizes, int n_in,
                              void* d_out, int out_size)
{
    const float* x  = (const float*)d_in[0];
    const float* Wq = (const float*)d_in[1];
    const float* bq = (const float*)d_in[2];
    const float* Wk = (const float*)d_in[3];
    const float* bk = (const float*)d_in[4];
    const float* Wv = (const float*)d_in[5];
    const float* bv = (const float*)d_in[6];
    float* out = (float*)d_out;

    float *pqp, *pkp, *pvT, *pattn;
    cudaGetSymbolAddress((void**)&pqp,  g_qp);
    cudaGetSymbolAddress((void**)&pkp,  g_kp);
    cudaGetSymbolAddress((void**)&pvT,  g_vT);
    cudaGetSymbolAddress((void**)&pattn, g_attn);

    const int SMEM_G = 3 * 2 * 16384;   // 96 KB
    cudaFuncSetAttribute(gemm_mma<true>,  cudaFuncAttributeMaxDynamicSharedMemorySize, SMEM_G);
    cudaFuncSetAttribute(gemm_mma<false>, cudaFuncAttributeMaxDynamicSharedMemorySize, SMEM_G);

    // 1) q,k packed hi/lo (permuted), vT (permuted)
    qkv_kernel<<<dim3(16, 16, BATCH), 256>>>(x, Wq, bq, Wk, bk, Wv, bv);

    // 2) logits = q k^T per batch (3xTF32, packed)
    gemm_mma<true><<<dim3(4, 4, BATCH), 256, SMEM_G>>>(pqp, pkp, pattn, 0);

    // 3) softmax rows (+ tf32 rounding + j-permutation)
    softmax_kernel<<<BATCH * 512, 128>>>();

    // 4) out = attn @ vT per (b,c), single tf32
    gemm_mma<false><<<dim3(4, 4, BATCH * 8), 256, SMEM_G>>>(pattn, pvT, out, 3);
}

// round 8
// speedup vs baseline: 1.9713x; 1.0268x over previous
#include <cuda_runtime.h>
#include <cstdint>

#define BATCH 16
#define HW    262144
#define NPIX  4194304

// ---------------- scratch (device globals; no runtime allocation) ----------
// q,k packed rows: per (b,h), 1024 floats = 32 groups x (16 hi | 16 lo), k-permuted
__device__ float g_qp[NPIX * 2], g_kp[NPIX * 2];
__device__ float g_vT[BATCH * 8 * HW];      // [B,C,W,H] (h k-permuted)
__device__ float g_attn[BATCH * HW];        // [B,H,H] (j k-permuted after softmax)

// ---------------- helpers ---------------------------------------------------
__device__ __forceinline__ float tf32r(float x) {
    uint32_t u; asm("cvt.rna.tf32.f32 %0, %1;" : "=r"(u) : "f"(x));
    return __uint_as_float(u);
}
__device__ __forceinline__ int kperm(int k) {
    return (k & ~15) | ((k & 3) << 2) | ((k >> 2) & 3);
}
#define CPA16(s, g)   asm volatile("cp.async.cg.shared.global [%0], [%1], 16;" :: "r"(s), "l"(g) : "memory")
#define CPA_COMMIT()  asm volatile("cp.async.commit_group;" ::: "memory")
#define CPA_WAIT(n)   asm volatile("cp.async.wait_group %0;" :: "n"(n) : "memory")

__device__ __forceinline__ uint32_t smem_u32(const void* p) {
    uint32_t a;
    asm("{ .reg .u64 t; cvta.to.shared.u64 t, %1; cvt.u32.u64 %0, t; }" : "=r"(a) : "l"(p));
    return a;
}
// chunk-level swizzle: row r (128B rows), 16B chunk ch (0..7).
// f depends only on r&7 -> rows differing by multiples of 8 share it.
__device__ __forceinline__ uint32_t swz128(int r, int ch) {
    const int f = ((r & 1) << 2) | ((r >> 1) & 3);
    return (uint32_t)(r * 128 + ((ch ^ f) << 4));
}
__device__ __forceinline__ uint4 lds128(uint32_t a) {
    uint4 v;
    asm volatile("ld.shared.v4.b32 {%0,%1,%2,%3}, [%4];"
                 : "=r"(v.x), "=r"(v.y), "=r"(v.z), "=r"(v.w) : "r"(a));
    return v;
}
#define MMA4(c, a0, a1, a2, a3, b0, b1) \
    asm volatile("mma.sync.aligned.m16n8k8.row.col.f32.tf32.tf32.f32 " \
                 "{%0,%1,%2,%3},{%4,%5,%6,%7},{%8,%9},{%0,%1,%2,%3};" \
                 : "+f"((c)[0]), "+f"((c)[1]), "+f"((c)[2]), "+f"((c)[3]) \
                 : "r"(a0), "r"(a1), "r"(a2), "r"(a3), "r"(b0), "r"(b1))

// ---------------------------------------------------------------------------
// Fused q/k/v 1x1 convs.  q,k written as packed hi/lo tf32 rows (1024 wide,
// k-permuted); v transposed to [B,C,W,H] (tf32, h k-permuted).
// ---------------------------------------------------------------------------
__global__ void __launch_bounds__(256)
qkv_kernel(const float* __restrict__ x,
           const float* __restrict__ Wq, const float* __restrict__ bq,
           const float* __restrict__ Wk, const float* __restrict__ bk,
           const float* __restrict__ Wv, const float* __restrict__ bv)
{
    __shared__ float sWq[8], sWk[8], sWv[64], sBv[8], sB2[2];
    __shared__ float sv[8][32][33];
    const int tid = threadIdx.x;
    if (tid < 8) { sWq[tid] = Wq[tid]; sWk[tid] = Wk[tid]; sBv[tid] = bv[tid]; }
    if (tid >= 8 && tid < 72) sWv[tid - 8] = Wv[tid - 8];
    if (tid == 72) sB2[0] = bq[0];
    if (tid == 73) sB2[1] = bk[0];
    __syncthreads();

    const int b = blockIdx.z, h0 = blockIdx.y * 32, w0 = blockIdx.x * 32;
    const int j = tid & 31, i0 = tid >> 5;

    for (int ii = 0; ii < 4; ii++) {
        const int i = i0 + ii * 8;
        const int h = h0 + i, w = w0 + j;
        const size_t pb = ((size_t)b * 8) * HW + (size_t)h * 512 + w;
        float xv[8];
#pragma unroll
        for (int c = 0; c < 8; c++) xv[c] = x[pb + (size_t)c * HW];

        float q = sB2[0], k = sB2[1];
#pragma unroll
        for (int c = 0; c < 8; c++) { q += xv[c] * sWq[c]; k += xv[c] * sWk[c]; }
        const int grp = w >> 4, pos = ((w & 3) << 2) | ((w >> 2) & 3);
        const size_t p = ((size_t)b * 512 + h) * 1024 + grp * 32 + pos;
        const float qh = tf32r(q), kh = tf32r(k);
        g_qp[p] = qh; g_qp[p + 16] = tf32r(q - qh);
        g_kp[p] = kh; g_kp[p + 16] = tf32r(k - kh);

#pragma unroll
        for (int o = 0; o < 8; o++) {
            float v = sBv[o];
#pragma unroll
            for (int c = 0; c < 8; c++) v += xv[c] * sWv[o * 8 + c];
            sv[o][i][j] = tf32r(v);
        }
    }
    __syncthreads();

    for (int ii = 0; ii < 4; ii++) {
        const int wl = i0 + ii * 8;
        const int hl = j;
#pragma unroll
        for (int c = 0; c < 8; c++) {
            g_vT[(((size_t)b * 8 + c) * 512 + (w0 + wl)) * 512 + kperm(h0 + hl)] = sv[c][hl][wl];
        }
    }
}

// ---------------------------------------------------------------------------
// mma.sync tf32 GEMM: C[m,n] = sum_k A[m,k]*B[n,k], per-z 512x512x512.
// 256 threads, 8 warps (4x2), CTA 128x128, warp tile 32x64.
// 3-stage cp.async pipeline, 32KB/stage -> 96KB -> 2 CTAs/SM.
// All SMEM fragment addresses = per-sel base register + compile-time imm.
//   SPLIT=false: rows 512 wide, 16 chunks of 32 k.
//   SPLIT=true : packed hi/lo rows 1024 wide, 32 chunks of 16 k, 3xTF32.
// ---------------------------------------------------------------------------
template <bool SPLIT>
__global__ void __launch_bounds__(256, 2)
gemm_mma(const float* __restrict__ Ab, const float* __restrict__ Bb,
         float* __restrict__ Cb, int aShift)
{
    constexpr int ROWLEN = SPLIT ? 1024 : 512;
    constexpr int NCH    = SPLIT ? 32 : 16;
    constexpr int STAGES = 3;
    constexpr uint32_t TA = 128 * 32 * 4;   // 16 KB per tile
    constexpr uint32_t SB = 2 * TA;         // 32 KB per stage

    extern __shared__ char smem[];
    const uint32_t s0 = smem_u32(smem);

    const int tid  = threadIdx.x;
    const int lane = tid & 31;
    const int wid  = tid >> 5;
    const int wm   = (wid & 3) * 32;
    const int wn   = (wid >> 2) * 64;
    const int gid  = lane >> 2;
    const int tig  = lane & 3;

    const int z = blockIdx.z;
    const size_t m0 = (size_t)blockIdx.y * 128;
    const size_t n0 = (size_t)blockIdx.x * 128;
    const float* A = Ab + (size_t)(z >> aShift) * 512 * ROWLEN;
    const float* B = Bb + (size_t)z * 512 * ROWLEN;
    float* C = Cb + (size_t)z * HW;

    // per-sel fragment bases (all other fragment addresses = base + imm)
    uint32_t bA[2], bB[2];
#pragma unroll
    for (int s = 0; s < 2; s++) {
        bA[s] = swz128(wm + gid, s * 4 + tig);
        bB[s] = TA + swz128(wn + gid, s * 4 + tig);
    }

    // loader: 256 threads -> (seg 0..7) x (row0 0..31), 4 rows (+32 apart) each
    const int seg  = tid & 7;
    const int row0 = tid >> 3;
    const uint32_t lsw0 = swz128(row0, seg);            // +i*4096 for row0+i*32
    const float* Arow = A + m0 * ROWLEN + (size_t)row0 * ROWLEN + seg * 4;
    const float* Brow = B + n0 * ROWLEN + (size_t)row0 * ROWLEN + seg * 4;

    auto load_chunk = [&](int c, uint32_t base) {
        const uint32_t sb = base + lsw0;
        const int go = c * 32;
#pragma unroll
        for (int i = 0; i < 4; i++) {
            CPA16(sb + i * 4096,      Arow + go + i * 32 * ROWLEN);
            CPA16(sb + TA + i * 4096, Brow + go + i * 32 * ROWLEN);
        }
    };

    float acc[2][8][4] = {};

    uint32_t stW = s0, stR = s0;
#pragma unroll
    for (int c = 0; c < STAGES - 1; c++) {
        load_chunk(c, stW); CPA_COMMIT();
        stW += SB; if (stW == s0 + STAGES * SB) stW = s0;
    }

    for (int c = 0; c < NCH; c++) {
        CPA_WAIT(STAGES - 2);
        __syncthreads();
        if (c + STAGES - 1 < NCH) load_chunk(c + STAGES - 1, stW);
        CPA_COMMIT();
        stW += SB; if (stW == s0 + STAGES * SB) stW = s0;

        const uint32_t sA = stR;
        stR += SB; if (stR == s0 + STAGES * SB) stR = s0;

        if (!SPLIT) {
#pragma unroll
            for (int g = 0; g < 2; g++) {
                const uint32_t aB = sA + bA[g];
                const uint32_t bBs = sA + bB[g];
                const uint4 a0 = lds128(aB);            // rows wm+gid .. (mt0 lo)
                const uint4 a1 = lds128(aB + 1024);     // +8  (mt0 hi)
                const uint4 a2 = lds128(aB + 2048);     // +16 (mt1 lo)
                const uint4 a3 = lds128(aB + 3072);     // +24 (mt1 hi)
#pragma unroll
                for (int nt = 0; nt < 8; nt++) {
                    const uint4 bv = lds128(bBs + nt * 1024);
                    MMA4(acc[0][nt], a0.x, a1.x, a0.y, a1.y, bv.x, bv.y);
                    MMA4(acc[0][nt], a0.z, a1.z, a0.w, a1.w, bv.z, bv.w);
                    MMA4(acc[1][nt], a2.x, a3.x, a2.y, a3.y, bv.x, bv.y);
                    MMA4(acc[1][nt], a2.z, a3.z, a2.w, a3.w, bv.z, bv.w);
                }
            }
        } else {
            const uint32_t ahB = sA + bA[0], alB = sA + bA[1];
            const uint32_t bhB = sA + bB[0], blB = sA + bB[1];
            const uint4 h0 = lds128(ahB),        h1 = lds128(ahB + 1024);
            const uint4 h2 = lds128(ahB + 2048), h3 = lds128(ahB + 3072);
            const uint4 l0 = lds128(alB),        l1 = lds128(alB + 1024);
            const uint4 l2 = lds128(alB + 2048), l3 = lds128(alB + 3072);
#pragma unroll
            for (int nt = 0; nt < 8; nt++) {
                const uint4 bh = lds128(bhB + nt * 1024);
                const uint4 bl = lds128(blB + nt * 1024);
                MMA4(acc[0][nt], h0.x, h1.x, h0.y, h1.y, bh.x, bh.y);
                MMA4(acc[0][nt], l0.x, l1.x, l0.y, l1.y, bh.x, bh.y);
                MMA4(acc[0][nt], h0.x, h1.x, h0.y, h1.y, bl.x, bl.y);
                MMA4(acc[0][nt], h0.z, h1.z, h0.w, h1.w, bh.z, bh.w);
                MMA4(acc[0][nt], l0.z, l1.z, l0.w, l1.w, bh.z, bh.w);
                MMA4(acc[0][nt], h0.z, h1.z, h0.w, h1.w, bl.z, bl.w);
                MMA4(acc[1][nt], h2.x, h3.x, h2.y, h3.y, bh.x, bh.y);
                MMA4(acc[1][nt], l2.x, l3.x, l2.y, l3.y, bh.x, bh.y);
                MMA4(acc[1][nt], h2.x, h3.x, h2.y, h3.y, bl.x, bl.y);
                MMA4(acc[1][nt], h2.z, h3.z, h2.w, h3.w, bh.z, bh.w);
                MMA4(acc[1][nt], l2.z, l3.z, l2.w, l3.w, bh.z, bh.w);
                MMA4(acc[1][nt], h2.z, h3.z, h2.w, h3.w, bl.z, bl.w);
            }
        }
    }

    // epilogue (natural n order)
#pragma unroll
    for (int mt = 0; mt < 2; mt++) {
        const size_t r0 = m0 + wm + mt * 16 + gid;
#pragma unroll
        for (int nt = 0; nt < 8; nt++) {
            const size_t cc = n0 + wn + nt * 8 + tig * 2;
            *(float2*)(C + r0 * 512 + cc)       = make_float2(acc[mt][nt][0], acc[mt][nt][1]);
            *(float2*)(C + (r0 + 8) * 512 + cc) = make_float2(acc[mt][nt][2], acc[mt][nt][3]);
        }
    }
}

// ---------------------------------------------------------------------------
// Row softmax over g_attn; reads natural order, writes k-permuted + tf32.
// ---------------------------------------------------------------------------
__global__ void softmax_kernel()
{
    const int row = blockIdx.x;
    const int tid = threadIdx.x;
    float* rp = g_attn + (size_t)row * 512;

    float4 v = *(float4*)(rp + tid * 4);
    float m = fmaxf(fmaxf(v.x, v.y), fmaxf(v.z, v.w));
#pragma unroll
    for (int o = 16; o > 0; o >>= 1) m = fmaxf(m, __shfl_xor_sync(0xFFFFFFFFu, m, o));

    __shared__ float sred[4];
    const int wid = tid >> 5, lane = tid & 31;
    if (lane == 0) sred[wid] = m;
    __syncthreads();
    m = fmaxf(fmaxf(sred[0], sred[1]), fmaxf(sred[2], sred[3]));
    __syncthreads();

    v.x = __expf(v.x - m); v.y = __expf(v.y - m);
    v.z = __expf(v.z - m); v.w = __expf(v.w - m);
    float s = v.x + v.y + v.z + v.w;
#pragma unroll
    for (int o = 16; o > 0; o >>= 1) s += __shfl_xor_sync(0xFFFFFFFFu, s, o);
    if (lane == 0) sred[wid] = s;
    __syncthreads();
    s = sred[0] + sred[1] + sred[2] + sred[3];

    const float inv = 1.0f / s;
    const int G = tid >> 2, u = tid & 3;
    float* gp = rp + G * 16 + u;
    __syncthreads();
    gp[0]  = tf32r(v.x * inv);
    gp[4]  = tf32r(v.y * inv);
    gp[8]  = tf32r(v.z * inv);
    gp[12] = tf32r(v.w * inv);
}

// ---------------------------------------------------------------------------
extern "C" void kernel_launch(void* const* d_in, const int* in_sizes, int n_in,
                              void* d_out, int out_size)
{
    const float* x  = (const float*)d_in[0];
    const float* Wq = (const float*)d_in[1];
    const float* bq = (const float*)d_in[2];
    const float* Wk = (const float*)d_in[3];
    const float* bk = (const float*)d_in[4];
    const float* Wv = (const float*)d_in[5];
    const float* bv = (const float*)d_in[6];
    float* out = (float*)d_out;

    float *pqp, *pkp, *pvT, *pattn;
    cudaGetSymbolAddress((void**)&pqp,  g_qp);
    cudaGetSymbolAddress((void**)&pkp,  g_kp);
    cudaGetSymbolAddress((void**)&pvT,  g_vT);
    cudaGetSymbolAddress((void**)&pattn, g_attn);

    const int SMEM_G = 3 * 2 * 16384;   // 96 KB
    cudaFuncSetAttribute(gemm_mma<true>,  cudaFuncAttributeMaxDynamicSharedMemorySize, SMEM_G);
    cudaFuncSetAttribute(gemm_mma<false>, cudaFuncAttributeMaxDynamicSharedMemorySize, SMEM_G);

    // 1) q,k packed hi/lo (permuted), vT (permuted)
    qkv_kernel<<<dim3(16, 16, BATCH), 256>>>(x, Wq, bq, Wk, bk, Wv, bv);

    // 2) logits = q k^T per batch (3xTF32, packed)
    gemm_mma<true><<<dim3(4, 4, BATCH), 256, SMEM_G>>>(pqp, pkp, pattn, 0);

    // 3) softmax rows (+ tf32 rounding + j-permutation)
    softmax_kernel<<<BATCH * 512, 128>>>();

    // 4) out = attn @ vT per (b,c), single tf32
    gemm_mma<false><<<dim3(4, 4, BATCH * 8), 256, SMEM_G>>>(pattn, pvT, out, 3);
}